// round 16
// baseline (speedup 1.0000x reference)
#include <cuda_runtime.h>
#include <cuda_fp16.h>
#include <cstdint>

#define BB    8
#define NVOX  16384
#define CC    512
#define C8    64
#define QKVN  192

// ---------------------------------------------------------------------------
// Scratch (device globals)
// ---------------------------------------------------------------------------
__device__ float g_v[BB * NVOX * C8];             // v only (33.5 MB)
__device__ float g_spart[BB * 256 * 64 * 64];     // per-CTA Gram partials (33.5 MB)
__device__ __half g_betaf[BB * 8192];             // beta in hi/lo B-fragment layout

// W1f: [T(16)][k16(2)][ntile(24)][lane(32)][hi0 hi1 lo0 lo1 (8 halfs)]
// W2f: [t(4)][hl(2)][ntile(64)][lane(32)][reg(2)][half(2)]
__device__ __half g_W1f[512 * 192 * 2];
__device__ float  g_b1[QKVN];
__device__ __half g_W2f[64 * 512 * 2];
__device__ float  g_b2[CC];

// ---------------------------------------------------------------------------
__device__ __forceinline__ void cpasync16(void* sdst, const void* g) {
    unsigned s = (unsigned)__cvta_generic_to_shared(sdst);
    asm volatile("cp.async.cg.shared.global [%0], [%1], 16;\n" :: "r"(s), "l"(g));
}
__device__ __forceinline__ void cpcommit() { asm volatile("cp.async.commit_group;\n"); }
__device__ __forceinline__ void cpwait0()  { asm volatile("cp.async.wait_group 0;\n"); }

__device__ __forceinline__ void ldmat4(uint32_t* r, const void* p) {
    uint32_t a = (uint32_t)__cvta_generic_to_shared(p);
    asm volatile("ldmatrix.sync.aligned.m8n8.x4.shared.b16 {%0,%1,%2,%3}, [%4];"
        : "=r"(r[0]), "=r"(r[1]), "=r"(r[2]), "=r"(r[3]) : "r"(a));
}

__device__ __forceinline__ void mma16(float* d, const uint32_t* a, const uint32_t* b) {
    asm("mma.sync.aligned.m16n8k16.row.col.f32.f16.f16.f32 "
        "{%0,%1,%2,%3},{%4,%5,%6,%7},{%8,%9},{%0,%1,%2,%3};"
        : "+f"(d[0]), "+f"(d[1]), "+f"(d[2]), "+f"(d[3])
        : "r"(a[0]), "r"(a[1]), "r"(a[2]), "r"(a[3]), "r"(b[0]), "r"(b[1]));
}

__device__ __forceinline__ int bfrag_idx(int t, int hl, int ntile, int NT, int k, int n) {
    int lane = ((n & 7) << 2) | ((k & 7) >> 1);
    int reg = (k >> 3) & 1;
    int halfsel = k & 1;
    return ((((t * 2 + hl) * NT + ntile) * 32 + lane) * 2 + reg) * 2 + halfsel;
}

__device__ __forceinline__ uint32_t pack_hi(float f0, float f1) {
    __half2 h = __halves2half2(__float2half(f0), __float2half(f1));
    return *(uint32_t*)&h;
}
__device__ __forceinline__ uint32_t pack_lo(float f0, float f1) {
    __half h0 = __float2half(f0), h1 = __float2half(f1);
    __half2 l = __halves2half2(__float2half(f0 - __half2float(h0)),
                               __float2half(f1 - __half2float(h1)));
    return *(uint32_t*)&l;
}

// ---------------------------------------------------------------------------
// K0: prep (single launch again)
// ---------------------------------------------------------------------------
__global__ __launch_bounds__(256) void prep_kernel(
    const float* __restrict__ g1, const float* __restrict__ be1,
    const float* __restrict__ m1, const float* __restrict__ v1,
    const float* __restrict__ wq, const float* __restrict__ bq,
    const float* __restrict__ wk, const float* __restrict__ bk,
    const float* __restrict__ wv, const float* __restrict__ bv,
    const float* __restrict__ wp, const float* __restrict__ bp,
    const float* __restrict__ g2, const float* __restrict__ be2,
    const float* __restrict__ m2, const float* __restrict__ v2)
{
    __shared__ float sA[CC], sT[CC];
    __shared__ float red[256];
    const int blk = blockIdx.x;
    const int tid = threadIdx.x;

    if (blk < 192) {
        for (int k = tid; k < CC; k += 256) {
            float a = g1[k] * rsqrtf(v1[k] + 1e-3f);
            sA[k] = a;
            sT[k] = be1[k] - m1[k] * a;
        }
        __syncthreads();
        const int n = blk;
        const float* w = (n < 64) ? wq : (n < 128) ? wk : wv;
        const int j = n & 63;
        const int ntile = n >> 3;
        float part = 0.f;
        for (int k = tid; k < CC; k += 256) {
            float wv_ = w[k * 64 + j];
            float val = sA[k] * wv_;
            __half hi = __float2half(val);
            __half lo = __float2half(val - __half2float(hi));
            int T = k >> 5, k16 = (k >> 4) & 1;
            int lane = ((n & 7) << 2) | ((k & 7) >> 1);
            int reg = (k >> 3) & 1, hs = k & 1;
            size_t base = ((((size_t)(T * 2 + k16) * 24 + ntile) * 32 + lane) * 8);
            g_W1f[base + reg * 2 + hs] = hi;
            g_W1f[base + 4 + reg * 2 + hs] = lo;
            part += sT[k] * wv_;
        }
        red[tid] = part; __syncthreads();
        for (int o = 128; o > 0; o >>= 1) { if (tid < o) red[tid] += red[tid + o]; __syncthreads(); }
        if (tid == 0) {
            float b0 = (n < 64) ? bq[j] : (n < 128) ? bk[j] : bv[j];
            g_b1[n] = b0 + red[0];
        }
    } else {
        for (int k = tid; k < CC; k += 256) {
            float a = g2[k] * rsqrtf(v2[k] + 1e-3f);
            sA[k] = a;
            sT[k] = be2[k] - m2[k] * a;
        }
        __syncthreads();
        const int n0 = (blk - 192) * 64;
        for (int idx = tid; idx < 64 * 64; idx += 256) {
            int n = n0 + (idx >> 6), k = idx & 63;
            float val = wp[k * CC + n] * sA[n];
            __half hi = __float2half(val);
            __half lo = __float2half(val - __half2float(hi));
            int t = k >> 4;
            g_W2f[bfrag_idx(t, 0, n >> 3, 64, k & 15, n & 7)] = hi;
            g_W2f[bfrag_idx(t, 1, n >> 3, 64, k & 15, n & 7)] = lo;
        }
        if (tid < 64) {
            int n = n0 + tid;
            g_b2[n] = bp[n] * sA[n] + sT[n];
        }
    }
}

// ---------------------------------------------------------------------------
// K1: QKV GEMM fp16x3 + fused Gram partial (identical to 342us best)
// ---------------------------------------------------------------------------
#define AST 56
#define ABUF_Q 7168
#define BBUF_Q 12288
#define SMEM_QKV ((2 * ABUF_Q + 2 * BBUF_Q) * 2)   // 77824 B

__global__ __launch_bounds__(256, 2) void gemm_qkv(const float* __restrict__ X)
{
    extern __shared__ __half smh[];
    __half* Abase = smh;
    __half* Bbase = smh + 2 * ABUF_Q;

    const int tid = threadIdx.x;
    const int wid = tid >> 5, lane = tid & 31;
    const int wm = wid & 1, wn = wid >> 1;
    const int m0 = blockIdx.x * 64;

    const int ar = tid >> 2;
    const int ac = (tid & 3) * 8;

    float acc[2][6][4];
#pragma unroll
    for (int i = 0; i < 2; i++)
#pragma unroll
        for (int j = 0; j < 6; j++)
#pragma unroll
            for (int q = 0; q < 4; q++) acc[i][j][q] = 0.f;

    float4 a0, a1;

    auto ldgA = [&](int t) {
        const float4* p = (const float4*)(X + (size_t)(m0 + ar) * CC + t * 32 + ac);
        a0 = p[0]; a1 = p[1];
    };
    auto stsA = [&](__half* Ab) {
        float vf[8] = {a0.x, a0.y, a0.z, a0.w, a1.x, a1.y, a1.z, a1.w};
        __half h[8], l[8];
#pragma unroll
        for (int q = 0; q < 8; q++) {
            h[q] = __float2half(vf[q]);
            l[q] = __float2half(vf[q] - __half2float(h[q]));
        }
        *(uint4*)&Ab[ar * AST + ac] = *(uint4*)h;
        *(uint4*)&Ab[(64 + ar) * AST + ac] = *(uint4*)l;
    };
    auto cpB = [&](int t, __half* Bb) {
        const __half* src = g_W1f + (size_t)t * BBUF_Q;
#pragma unroll
        for (int i = 0; i < 6; i++) {
            int v = tid + i * 256;
            cpasync16(&Bb[v * 8], src + v * 8);
        }
    };
    auto compute = [&](const __half* Ab, const __half* Bb) {
#pragma unroll
        for (int s = 0; s < 2; s++) {
            uint32_t af[2][2][4];
#pragma unroll
            for (int mi = 0; mi < 2; mi++)
#pragma unroll
                for (int hl = 0; hl < 2; hl++)
                    ldmat4(af[mi][hl],
                           &Ab[(hl * 64 + wm * 32 + mi * 16 + (lane & 15)) * AST
                               + s * 16 + (lane >> 4) * 8]);
            uint32_t bh[6][2], bl[6][2];
#pragma unroll
            for (int ni = 0; ni < 6; ni++) {
                int nt = wn * 6 + ni;
                uint4 bv = *(const uint4*)&Bb[((s * 24 + nt) * 32 + lane) * 8];
                bh[ni][0] = bv.x; bh[ni][1] = bv.y;
                bl[ni][0] = bv.z; bl[ni][1] = bv.w;
            }
#pragma unroll
            for (int ni = 0; ni < 6; ni++)
#pragma unroll
                for (int mi = 0; mi < 2; mi++)
                    mma16(acc[mi][ni], af[mi][0], bh[ni]);
#pragma unroll
            for (int ni = 0; ni < 6; ni++)
#pragma unroll
                for (int mi = 0; mi < 2; mi++)
                    mma16(acc[mi][ni], af[mi][0], bl[ni]);
#pragma unroll
            for (int ni = 0; ni < 6; ni++)
#pragma unroll
                for (int mi = 0; mi < 2; mi++)
                    mma16(acc[mi][ni], af[mi][1], bh[ni]);
        }
    };

    ldgA(0);
    cpB(0, Bbase);
    cpcommit();
    stsA(Abase);

    for (int t = 0; t < 16; t++) {
        __half* Ac = Abase + (t & 1) * ABUF_Q;
        __half* Bc = Bbase + (t & 1) * BBUF_Q;
        __half* An = Abase + ((t + 1) & 1) * ABUF_Q;
        __half* Bn = Bbase + ((t + 1) & 1) * BBUF_Q;
        if (t + 1 < 16) ldgA(t + 1);
        cpwait0();
        __syncthreads();
        if (t + 1 < 16) { cpB(t + 1, Bn); cpcommit(); }
        compute(Ac, Bc);
        if (t + 1 < 16) stsA(An);
    }

    // ---- Epilogue: stage q,k (+bias) to smem; write v (+bias) to gmem ----
    __syncthreads();
    float* Sf = (float*)smh;              // S[64][132]: cols 0-63 = q, 64-127 = k
    const int gid = lane >> 2, tg = lane & 3;
#pragma unroll
    for (int mi = 0; mi < 2; mi++) {
        int r = wm * 32 + mi * 16 + gid;
#pragma unroll
        for (int ni = 0; ni < 6; ni++) {
            int c = wn * 48 + ni * 8 + tg * 2;
            float b0 = g_b1[c], b1v = g_b1[c + 1];
            float v0x = acc[mi][ni][0] + b0, v0y = acc[mi][ni][1] + b1v;
            float v1x = acc[mi][ni][2] + b0, v1y = acc[mi][ni][3] + b1v;
            if (c < 128) {
                Sf[r * 132 + c] = v0x;       Sf[r * 132 + c + 1] = v0y;
                Sf[(r + 8) * 132 + c] = v1x; Sf[(r + 8) * 132 + c + 1] = v1y;
            } else {
                int col = c - 128;
                *(float2*)&g_v[(size_t)(m0 + r) * C8 + col] = make_float2(v0x, v0y);
                *(float2*)&g_v[(size_t)(m0 + r + 8) * C8 + col] = make_float2(v1x, v1y);
            }
        }
    }
    __syncthreads();

    // ---- Fused Gram partial (pass-major) ----
    const int b  = blockIdx.x >> 8;
    const int ch = blockIdx.x & 255;
    const int i0 = (wid & 3) * 16;
    const int j0 = (wid >> 2) * 32;
    const int rl = lane >> 2;
    const int cb = (lane & 3) * 2;

    float p[4][4];
#pragma unroll
    for (int jt = 0; jt < 4; jt++)
#pragma unroll
        for (int q = 0; q < 4; q++) p[jt][q] = 0.f;

#pragma unroll
    for (int kk = 0; kk < 4; kk++) {
        const int nb = kk * 16;
        uint32_t ah[4], al[4];
#pragma unroll
        for (int fr = 0; fr < 4; fr++) {
            int nn = nb + cb + (fr >> 1) * 8;
            int ii = i0 + rl + (fr & 1) * 8;
            float f0 = Sf[nn * 132 + ii];
            float f1 = Sf[(nn + 1) * 132 + ii];
            ah[fr] = pack_hi(f0, f1);
            al[fr] = pack_lo(f0, f1);
        }
        uint32_t bh[4][2], bl[4][2];
#pragma unroll
        for (int jt = 0; jt < 4; jt++) {
            int jj = 64 + j0 + jt * 8 + rl;
#pragma unroll
            for (int br = 0; br < 2; br++) {
                int nn = nb + cb + br * 8;
                float f0 = Sf[nn * 132 + jj];
                float f1 = Sf[(nn + 1) * 132 + jj];
                bh[jt][br] = pack_hi(f0, f1);
                bl[jt][br] = pack_lo(f0, f1);
            }
        }
#pragma unroll
        for (int jt = 0; jt < 4; jt++) mma16(p[jt], ah, bh[jt]);
#pragma unroll
        for (int jt = 0; jt < 4; jt++) mma16(p[jt], ah, bl[jt]);
#pragma unroll
        for (int jt = 0; jt < 4; jt++) mma16(p[jt], al, bh[jt]);
    }

#pragma unroll
    for (int jt = 0; jt < 4; jt++) {
        size_t base = (((size_t)(b * 256 + ch) * 64) + i0 + rl) * 64 + j0 + jt * 8 + cb;
        *(float2*)&g_spart[base] = make_float2(p[jt][0], p[jt][1]);
        *(float2*)&g_spart[base + 8 * 64] = make_float2(p[jt][2], p[jt][3]);
    }
}

// ---------------------------------------------------------------------------
// K3: reduce 256 Gram partials + row softmax; emit beta in fragment layout
// ---------------------------------------------------------------------------
__global__ __launch_bounds__(256) void softmax_kernel()
{
    const int m = blockIdx.x, b = blockIdx.y;
    const int tid = threadIdx.x;
    const int j = tid & 63, cp = tid >> 6;

    float s = 0.f;
    const float* base = g_spart + (((size_t)(b * 256 + cp * 64)) * 64 + m) * 64 + j;
#pragma unroll 4
    for (int cc = 0; cc < 64; cc++)
        s += base[(size_t)cc * 4096];

    __shared__ float red[4][64];
    __shared__ float r2[64];
    red[cp][j] = s;
    __syncthreads();
    float tot = red[0][j] + red[1][j] + red[2][j] + red[3][j];

    if (cp == 0) r2[j] = tot;
    __syncthreads();
    for (int o = 32; o > 0; o >>= 1) {
        if (cp == 0 && j < o) r2[j] = fmaxf(r2[j], r2[j + o]);
        __syncthreads();
    }
    float mx = r2[0];
    __syncthreads();
    float e = expf(tot - mx);
    if (cp == 0) r2[j] = e;
    __syncthreads();
    for (int o = 32; o > 0; o >>= 1) {
        if (cp == 0 && j < o) r2[j] += r2[j + o];
        __syncthreads();
    }
    if (cp == 0) {
        float val = e / r2[0];
        __half hi = __float2half(val);
        __half lo = __float2half(val - __half2float(hi));
        int t = m >> 4;
        size_t bb = (size_t)b * 8192;
        g_betaf[bb + bfrag_idx(t, 0, j >> 3, 8, m & 15, j & 7)] = hi;
        g_betaf[bb + bfrag_idx(t, 1, j >> 3, 8, m & 15, j & 7)] = lo;
    }
}

// ---------------------------------------------------------------------------
// K4: FUSED av + proj.
// Phase 1: A64x64 = v(64 rows) @ beta  -> Os[d][i] in smem (d=v-row, i=col).
// Phase 2: out rows p = i*256 + j0:  Out[p, :] = Os[:, i]^T @ W2 + b2.
// smem (halfs): [0..16384) proj B dbl buf | [16384..24832) Os (4224 f32)
//               [24832..37120) Ap frags.  Phase-1 pipeline reuses [0..14336).
// ---------------------------------------------------------------------------
#define ABUF_AV 3072
#define OSST 66
#define OS_OFF 16384      // half offset of Os
#define AP_OFF 24832      // half offset of Ap
#define SMEM_AVPROJ 74240

__global__ __launch_bounds__(256) void avproj_gemm(float* __restrict__ Out)
{
    extern __shared__ __half smh[];
    const int tid = threadIdx.x;
    const int wid = tid >> 5, lane = tid & 31;
    const int wm = wid & 1, wn = wid >> 1;
    const int j0 = blockIdx.x;          // chunk 0..255
    const int b  = blockIdx.y;
    const int n0 = j0 * 64;

    float* Os = (float*)(smh + OS_OFF);
    __half* Ap = smh + AP_OFF;

    // ================= Phase 1: av tile =================
    {
        __half* Ab0 = smh;
        __half* Ab1 = smh + ABUF_AV;
        __half* Bf  = smh + 2 * ABUF_AV;

        const int ar = tid >> 2;
        const int ac = (tid & 3) * 4;

        float acc[2][2][4];
#pragma unroll
        for (int i = 0; i < 2; i++)
#pragma unroll
            for (int j = 0; j < 2; j++)
#pragma unroll
                for (int q = 0; q < 4; q++) acc[i][j][q] = 0.f;

        float4 areg;
        auto ldgA = [&](int t) {
            areg = *(const float4*)(g_v + (size_t)(b * NVOX + n0 + ar) * C8 + t * 16 + ac);
        };
        auto stsA = [&](__half* Ab) {
            float vv[4] = {areg.x, areg.y, areg.z, areg.w};
            __half h[4], l[4];
#pragma unroll
            for (int q = 0; q < 4; q++) {
                h[q] = __float2half(vv[q]);
                l[q] = __float2half(vv[q] - __half2float(h[q]));
            }
            *(uint2*)&Ab[ar * 24 + ac] = *(uint2*)h;
            *(uint2*)&Ab[(64 + ar) * 24 + ac] = *(uint2*)l;
        };

        {
            const __half* src = g_betaf + (size_t)b * 8192;
#pragma unroll
            for (int i = 0; i < 4; i++) {
                int v = tid + i * 256;
                cpasync16(&Bf[v * 8], src + v * 8);
            }
            cpcommit();
        }
        ldgA(0);
        stsA(Ab0);
        cpwait0();
        __syncthreads();

#pragma unroll
        for (int t = 0; t < 4; t++) {
            __half* Ac = (t & 1) ? Ab1 : Ab0;
            __half* An = (t & 1) ? Ab0 : Ab1;
            if (t + 1 < 4) ldgA(t + 1);

            uint32_t af[2][2][4];
#pragma unroll
            for (int mi = 0; mi < 2; mi++)
#pragma unroll
                for (int hl = 0; hl < 2; hl++)
                    ldmat4(af[mi][hl],
                           &Ac[(hl * 64 + wm * 32 + mi * 16 + (lane & 15)) * 24 + (lane >> 4) * 8]);
            uint32_t bh[2][2], bl[2][2];
#pragma unroll
            for (int ni = 0; ni < 2; ni++) {
                int ntile = wn * 2 + ni;
                *(uint2*)bh[ni] = *(const uint2*)&Bf[(((t * 2 + 0) * 8 + ntile) * 32 + lane) * 4];
                *(uint2*)bl[ni] = *(const uint2*)&Bf[(((t * 2 + 1) * 8 + ntile) * 32 + lane) * 4];
            }
#pragma unroll
            for (int ni = 0; ni < 2; ni++)
#pragma unroll
                for (int mi = 0; mi < 2; mi++) {
                    mma16(acc[mi][ni], af[mi][0], bh[ni]);
                    mma16(acc[mi][ni], af[mi][0], bl[ni]);
                    mma16(acc[mi][ni], af[mi][1], bh[ni]);
                }

            if (t + 1 < 4) { stsA(An); __syncthreads(); }
        }

        // Os[d][i] = A[v-row d][col i]
        __syncthreads();
        const int gid = lane >> 2, tg = lane & 3;
#pragma unroll
        for (int mi = 0; mi < 2; mi++) {
            int r = wm * 32 + mi * 16 + gid;
#pragma unroll
            for (int ni = 0; ni < 2; ni++) {
                int c = wn * 16 + ni * 8 + tg * 2;
                *(float2*)&Os[r * OSST + c] = make_float2(acc[mi][ni][0], acc[mi][ni][1]);
                *(float2*)&Os[(r + 8) * OSST + c] = make_float2(acc[mi][ni][2], acc[mi][ni][3]);
            }
        }
    }
    __syncthreads();

    // ================= Phase 2: proj on 64 rows =================
    __half* Bb0 = smh;
    __half* Bb1 = smh + 8192;

    auto cpBp = [&](int nh, int t, __half* Bb) {
#pragma unroll
        for (int hl = 0; hl < 2; hl++) {
            const __half* src = g_W2f + ((size_t)(t * 2 + hl) * 64 + nh * 32) * 128;
#pragma unroll
            for (int i = 0; i < 2; i++) {
                int v = tid + i * 256;
                cpasync16(&Bb[hl * 4096 + v * 8], src + v * 8);
            }
        }
        cpcommit();
    };

    // start nh=0 t=0 B copy; overlap with Ap fill
    cpBp(0, 0, Bb0);

    // Ap[t][hl][i(64)][24]: A_proj[i][d] = Os[d][i]
    {
        const int ir = tid >> 2;           // i row
        const int dc = (tid & 3) * 4;      // 4 cols within 16-chunk
#pragma unroll
        for (int t = 0; t < 4; t++) {
            __half h[4], l[4];
#pragma unroll
            for (int q = 0; q < 4; q++) {
                float f = Os[(t * 16 + dc + q) * OSST + ir];
                h[q] = __float2half(f);
                l[q] = __float2half(f - __half2float(h[q]));
            }
            *(uint2*)&Ap[((t * 2 + 0) * 64 + ir) * 24 + dc] = *(uint2*)h;
            *(uint2*)&Ap[((t * 2 + 1) * 64 + ir) * 24 + dc] = *(uint2*)l;
        }
    }
    __syncthreads();

    const int gid = lane >> 2, tg = lane & 3;

#pragma unroll
    for (int nh = 0; nh < 2; nh++) {
        if (nh == 1) {
            __syncthreads();         // everyone done reading B bufs from nh=0
            cpBp(1, 0, Bb0);
        }
        float acc[2][8][4];
#pragma unroll
        for (int i = 0; i < 2; i++)
#pragma unroll
            for (int j = 0; j < 8; j++)
#pragma unroll
                for (int q = 0; q < 4; q++) acc[i][j][q] = 0.f;

#pragma unroll
        for (int t = 0; t < 4; t++) {
            __half* Bc = (t & 1) ? Bb1 : Bb0;
            __half* Bn = (t & 1) ? Bb0 : Bb1;
            cpwait0();
            __syncthreads();
            if (t + 1 < 4) cpBp(nh, t + 1, Bn);

            uint32_t af[2][2][4];
#pragma unroll
            for (int mi = 0; mi < 2; mi++)
#pragma unroll
                for (int hl = 0; hl < 2; hl++)
                    ldmat4(af[mi][hl],
                           &Ap[((t * 2 + hl) * 64 + wm * 32 + mi * 16 + (lane & 15)) * 24
                               + (lane >> 4) * 8]);
#pragma unroll
            for (int ni = 0; ni < 8; ni++) {
                int ntl = wn * 8 + ni;
                uint32_t bh[2], bl[2];
                *(uint2*)bh = *(const uint2*)&Bc[(ntl * 32 + lane) * 4];
                *(uint2*)bl = *(const uint2*)&Bc[4096 + (ntl * 32 + lane) * 4];
#pragma unroll
                for (int mi = 0; mi < 2; mi++) {
                    mma16(acc[mi][ni], af[mi][0], bh);
                    mma16(acc[mi][ni], af[mi][0], bl);
                    mma16(acc[mi][ni], af[mi][1], bh);
                }
            }
        }

        // Epilogue: out row p = i*256 + j0
#pragma unroll
        for (int mi = 0; mi < 2; mi++) {
            int i0r = wm * 32 + mi * 16 + gid;
            size_t row0 = (size_t)(b * NVOX + i0r * 256 + j0);
            size_t row1 = (size_t)(b * NVOX + (i0r + 8) * 256 + j0);
#pragma unroll
            for (int ni = 0; ni < 8; ni++) {
                int col = nh * 256 + wn * 64 + ni * 8 + tg * 2;
                float b0 = g_b2[col], b1 = g_b2[col + 1];
                float2 v0 = make_float2(acc[mi][ni][0] + b0, acc[mi][ni][1] + b1);
                float2 v1 = make_float2(acc[mi][ni][2] + b0, acc[mi][ni][3] + b1);
                *(float2*)&Out[row0 * CC + col] = v0;
                *(float2*)&Out[row1 * CC + col] = v1;
            }
        }
    }
}

// ---------------------------------------------------------------------------
extern "C" void kernel_launch(void* const* d_in, const int* in_sizes, int n_in,
                              void* d_out, int out_size)
{
    const float* x   = (const float*)d_in[0];
    const float* g1  = (const float*)d_in[1];
    const float* be1 = (const float*)d_in[2];
    const float* m1  = (const float*)d_in[3];
    const float* v1  = (const float*)d_in[4];
    const float* wq  = (const float*)d_in[5];
    const float* bq  = (const float*)d_in[6];
    const float* wk  = (const float*)d_in[7];
    const float* bk  = (const float*)d_in[8];
    const float* wv  = (const float*)d_in[9];
    const float* bv  = (const float*)d_in[10];
    const float* wp  = (const float*)d_in[11];
    const float* bp  = (const float*)d_in[12];
    const float* g2  = (const float*)d_in[13];
    const float* be2 = (const float*)d_in[14];
    const float* m2  = (const float*)d_in[15];
    const float* v2  = (const float*)d_in[16];
    float* out = (float*)d_out;

    cudaFuncSetAttribute(gemm_qkv,   cudaFuncAttributeMaxDynamicSharedMemorySize, SMEM_QKV);
    cudaFuncSetAttribute(avproj_gemm, cudaFuncAttributeMaxDynamicSharedMemorySize, SMEM_AVPROJ);

    prep_kernel<<<200, 256>>>(g1, be1, m1, v1, wq, bq, wk, bk, wv, bv,
                              wp, bp, g2, be2, m2, v2);

    // QKV GEMM + fused per-CTA Gram partials
    gemm_qkv<<<(BB * NVOX) / 64, 256, SMEM_QKV>>>(x);

    // reduce partials + softmax -> beta fragments
    softmax_kernel<<<dim3(64, BB), 256>>>();

    // FUSED: A = v@beta, then proj + BN2 -> final output (4th launch, profiled)
    avproj_gemm<<<dim3(NVOX / 64, BB), 256, SMEM_AVPROJ>>>(out);
}

// round 17
// speedup vs baseline: 1.0703x; 1.0703x over previous
#include <cuda_runtime.h>
#include <cuda_fp16.h>
#include <cstdint>

#define BB    8
#define NVOX  16384
#define CC    512
#define C8    64
#define QKVN  192

// ---------------------------------------------------------------------------
// Scratch (device globals)
// ---------------------------------------------------------------------------
__device__ float g_v[BB * NVOX * C8];             // v only (33.5 MB)
__device__ float g_spart[BB * 256 * 64 * 64];     // per-CTA Gram partials (33.5 MB)
__device__ __half g_betaf[BB * 8192];             // beta in hi/lo B-fragment layout
__device__ float g_Ag[BB * NVOX * C8];

// W1f: [T(16)][k16(2)][ntile(24)][lane(32)][hi0 hi1 lo0 lo1 (8 halfs)]
// W2f: [t(4)][hl(2)][ntile(64)][lane(32)][reg(2)][half(2)]
__device__ __half g_W1f[512 * 192 * 2];
__device__ float  g_b1[QKVN];
__device__ __half g_W2f[64 * 512 * 2];
__device__ float  g_b2[CC];

// ---------------------------------------------------------------------------
__device__ __forceinline__ void cpasync16(void* sdst, const void* g) {
    unsigned s = (unsigned)__cvta_generic_to_shared(sdst);
    asm volatile("cp.async.cg.shared.global [%0], [%1], 16;\n" :: "r"(s), "l"(g));
}
__device__ __forceinline__ void cpcommit() { asm volatile("cp.async.commit_group;\n"); }
__device__ __forceinline__ void cpwait0()  { asm volatile("cp.async.wait_group 0;\n"); }
__device__ __forceinline__ void cpwait1()  { asm volatile("cp.async.wait_group 1;\n"); }

__device__ __forceinline__ void ldmat4(uint32_t* r, const void* p) {
    uint32_t a = (uint32_t)__cvta_generic_to_shared(p);
    asm volatile("ldmatrix.sync.aligned.m8n8.x4.shared.b16 {%0,%1,%2,%3}, [%4];"
        : "=r"(r[0]), "=r"(r[1]), "=r"(r[2]), "=r"(r[3]) : "r"(a));
}

// NON-volatile: register-only semantics; lets ptxas schedule/interleave MMAs.
__device__ __forceinline__ void mma16(float* d, const uint32_t* a, const uint32_t* b) {
    asm("mma.sync.aligned.m16n8k16.row.col.f32.f16.f16.f32 "
        "{%0,%1,%2,%3},{%4,%5,%6,%7},{%8,%9},{%0,%1,%2,%3};"
        : "+f"(d[0]), "+f"(d[1]), "+f"(d[2]), "+f"(d[3])
        : "r"(a[0]), "r"(a[1]), "r"(a[2]), "r"(a[3]), "r"(b[0]), "r"(b[1]));
}

__device__ __forceinline__ int bfrag_idx(int t, int hl, int ntile, int NT, int k, int n) {
    int lane = ((n & 7) << 2) | ((k & 7) >> 1);
    int reg = (k >> 3) & 1;
    int halfsel = k & 1;
    return ((((t * 2 + hl) * NT + ntile) * 32 + lane) * 2 + reg) * 2 + halfsel;
}

__device__ __forceinline__ uint32_t pack_hi(float f0, float f1) {
    __half2 h = __halves2half2(__float2half(f0), __float2half(f1));
    return *(uint32_t*)&h;
}
__device__ __forceinline__ uint32_t pack_lo(float f0, float f1) {
    __half h0 = __float2half(f0), h1 = __float2half(f1);
    __half2 l = __halves2half2(__float2half(f0 - __half2float(h0)),
                               __float2half(f1 - __half2float(h1)));
    return *(uint32_t*)&l;
}

// ---------------------------------------------------------------------------
// K0: prep
// ---------------------------------------------------------------------------
__global__ __launch_bounds__(256) void prep_kernel(
    const float* __restrict__ g1, const float* __restrict__ be1,
    const float* __restrict__ m1, const float* __restrict__ v1,
    const float* __restrict__ wq, const float* __restrict__ bq,
    const float* __restrict__ wk, const float* __restrict__ bk,
    const float* __restrict__ wv, const float* __restrict__ bv,
    const float* __restrict__ wp, const float* __restrict__ bp,
    const float* __restrict__ g2, const float* __restrict__ be2,
    const float* __restrict__ m2, const float* __restrict__ v2)
{
    __shared__ float sA[CC], sT[CC];
    __shared__ float red[256];
    const int blk = blockIdx.x;
    const int tid = threadIdx.x;

    if (blk < 192) {
        for (int k = tid; k < CC; k += 256) {
            float a = g1[k] * rsqrtf(v1[k] + 1e-3f);
            sA[k] = a;
            sT[k] = be1[k] - m1[k] * a;
        }
        __syncthreads();
        const int n = blk;
        const float* w = (n < 64) ? wq : (n < 128) ? wk : wv;
        const int j = n & 63;
        const int ntile = n >> 3;
        float part = 0.f;
        for (int k = tid; k < CC; k += 256) {
            float wv_ = w[k * 64 + j];
            float val = sA[k] * wv_;
            __half hi = __float2half(val);
            __half lo = __float2half(val - __half2float(hi));
            int T = k >> 5, k16 = (k >> 4) & 1;
            int lane = ((n & 7) << 2) | ((k & 7) >> 1);
            int reg = (k >> 3) & 1, hs = k & 1;
            size_t base = ((((size_t)(T * 2 + k16) * 24 + ntile) * 32 + lane) * 8);
            g_W1f[base + reg * 2 + hs] = hi;
            g_W1f[base + 4 + reg * 2 + hs] = lo;
            part += sT[k] * wv_;
        }
        red[tid] = part; __syncthreads();
        for (int o = 128; o > 0; o >>= 1) { if (tid < o) red[tid] += red[tid + o]; __syncthreads(); }
        if (tid == 0) {
            float b0 = (n < 64) ? bq[j] : (n < 128) ? bk[j] : bv[j];
            g_b1[n] = b0 + red[0];
        }
    } else {
        for (int k = tid; k < CC; k += 256) {
            float a = g2[k] * rsqrtf(v2[k] + 1e-3f);
            sA[k] = a;
            sT[k] = be2[k] - m2[k] * a;
        }
        __syncthreads();
        const int n0 = (blk - 192) * 64;
        for (int idx = tid; idx < 64 * 64; idx += 256) {
            int n = n0 + (idx >> 6), k = idx & 63;
            float val = wp[k * CC + n] * sA[n];
            __half hi = __float2half(val);
            __half lo = __float2half(val - __half2float(hi));
            int t = k >> 4;
            g_W2f[bfrag_idx(t, 0, n >> 3, 64, k & 15, n & 7)] = hi;
            g_W2f[bfrag_idx(t, 1, n >> 3, 64, k & 15, n & 7)] = lo;
        }
        if (tid < 64) {
            int n = n0 + tid;
            g_b2[n] = bp[n] * sA[n] + sT[n];
        }
    }
}

// ---------------------------------------------------------------------------
// K1: QKV GEMM fp16x3 + fused Gram partial.
// 3-stage B ring (wait_group 1 -> two compute phases of cp.async slack).
// ---------------------------------------------------------------------------
#define AST 56
#define ABUF_Q 7168
#define BBUF_Q 12288
#define SMEM_QKV ((2 * ABUF_Q + 3 * BBUF_Q) * 2)   // 102400 B, 2 CTAs/SM

__global__ __launch_bounds__(256, 2) void gemm_qkv(const float* __restrict__ X)
{
    extern __shared__ __half smh[];
    __half* Abase = smh;
    __half* Bbase = smh + 2 * ABUF_Q;

    const int tid = threadIdx.x;
    const int wid = tid >> 5, lane = tid & 31;
    const int wm = wid & 1, wn = wid >> 1;
    const int m0 = blockIdx.x * 64;

    const int ar = tid >> 2;
    const int ac = (tid & 3) * 8;

    float acc[2][6][4];
#pragma unroll
    for (int i = 0; i < 2; i++)
#pragma unroll
        for (int j = 0; j < 6; j++)
#pragma unroll
            for (int q = 0; q < 4; q++) acc[i][j][q] = 0.f;

    float4 a0, a1;

    auto ldgA = [&](int t) {
        const float4* p = (const float4*)(X + (size_t)(m0 + ar) * CC + t * 32 + ac);
        a0 = p[0]; a1 = p[1];
    };
    auto stsA = [&](__half* Ab) {
        float vf[8] = {a0.x, a0.y, a0.z, a0.w, a1.x, a1.y, a1.z, a1.w};
        __half h[8], l[8];
#pragma unroll
        for (int q = 0; q < 8; q++) {
            h[q] = __float2half(vf[q]);
            l[q] = __float2half(vf[q] - __half2float(h[q]));
        }
        *(uint4*)&Ab[ar * AST + ac] = *(uint4*)h;
        *(uint4*)&Ab[(64 + ar) * AST + ac] = *(uint4*)l;
    };
    auto cpB = [&](int t) {
        __half* Bb = Bbase + (t % 3) * BBUF_Q;
        const __half* src = g_W1f + (size_t)t * BBUF_Q;
#pragma unroll
        for (int i = 0; i < 6; i++) {
            int v = tid + i * 256;
            cpasync16(&Bb[v * 8], src + v * 8);
        }
        cpcommit();
    };
    auto compute = [&](const __half* Ab, const __half* Bb) {
#pragma unroll
        for (int s = 0; s < 2; s++) {
            uint32_t af[2][2][4];
#pragma unroll
            for (int mi = 0; mi < 2; mi++)
#pragma unroll
                for (int hl = 0; hl < 2; hl++)
                    ldmat4(af[mi][hl],
                           &Ab[(hl * 64 + wm * 32 + mi * 16 + (lane & 15)) * AST
                               + s * 16 + (lane >> 4) * 8]);
            uint32_t bh[6][2], bl[6][2];
#pragma unroll
            for (int ni = 0; ni < 6; ni++) {
                int nt = wn * 6 + ni;
                uint4 bv = *(const uint4*)&Bb[((s * 24 + nt) * 32 + lane) * 8];
                bh[ni][0] = bv.x; bh[ni][1] = bv.y;
                bl[ni][0] = bv.z; bl[ni][1] = bv.w;
            }
#pragma unroll
            for (int ni = 0; ni < 6; ni++)
#pragma unroll
                for (int mi = 0; mi < 2; mi++)
                    mma16(acc[mi][ni], af[mi][0], bh[ni]);
#pragma unroll
            for (int ni = 0; ni < 6; ni++)
#pragma unroll
                for (int mi = 0; mi < 2; mi++)
                    mma16(acc[mi][ni], af[mi][0], bl[ni]);
#pragma unroll
            for (int ni = 0; ni < 6; ni++)
#pragma unroll
                for (int mi = 0; mi < 2; mi++)
                    mma16(acc[mi][ni], af[mi][1], bh[ni]);
        }
    };

    ldgA(0);
    cpB(0);
    cpB(1);
    stsA(Abase);

    for (int t = 0; t < 16; t++) {
        __half* Ac = Abase + (t & 1) * ABUF_Q;
        __half* Bc = Bbase + (t % 3) * BBUF_Q;
        __half* An = Abase + ((t + 1) & 1) * ABUF_Q;
        if (t + 1 < 16) ldgA(t + 1);
        if (t + 2 < 16) cpwait1(); else cpwait0();   // stage t guaranteed landed
        __syncthreads();
        if (t + 2 < 16) cpB(t + 2);                  // refill buf (t+2)%3 == (t-1)%3
        compute(Ac, Bc);
        if (t + 1 < 16) stsA(An);
    }

    // ---- Epilogue: stage q,k (+bias) to smem; write v (+bias) to gmem ----
    __syncthreads();
    float* Sf = (float*)smh;              // S[64][132]: cols 0-63 = q, 64-127 = k
    const int gid = lane >> 2, tg = lane & 3;
#pragma unroll
    for (int mi = 0; mi < 2; mi++) {
        int r = wm * 32 + mi * 16 + gid;
#pragma unroll
        for (int ni = 0; ni < 6; ni++) {
            int c = wn * 48 + ni * 8 + tg * 2;
            float b0 = g_b1[c], b1v = g_b1[c + 1];
            float v0x = acc[mi][ni][0] + b0, v0y = acc[mi][ni][1] + b1v;
            float v1x = acc[mi][ni][2] + b0, v1y = acc[mi][ni][3] + b1v;
            if (c < 128) {
                Sf[r * 132 + c] = v0x;       Sf[r * 132 + c + 1] = v0y;
                Sf[(r + 8) * 132 + c] = v1x; Sf[(r + 8) * 132 + c + 1] = v1y;
            } else {
                int col = c - 128;
                *(float2*)&g_v[(size_t)(m0 + r) * C8 + col] = make_float2(v0x, v0y);
                *(float2*)&g_v[(size_t)(m0 + r + 8) * C8 + col] = make_float2(v1x, v1y);
            }
        }
    }
    __syncthreads();

    // ---- Fused Gram partial (pass-major) ----
    const int b  = blockIdx.x >> 8;
    const int ch = blockIdx.x & 255;
    const int i0 = (wid & 3) * 16;
    const int j0 = (wid >> 2) * 32;
    const int rl = lane >> 2;
    const int cb = (lane & 3) * 2;

    float p[4][4];
#pragma unroll
    for (int jt = 0; jt < 4; jt++)
#pragma unroll
        for (int q = 0; q < 4; q++) p[jt][q] = 0.f;

#pragma unroll
    for (int kk = 0; kk < 4; kk++) {
        const int nb = kk * 16;
        uint32_t ah[4], al[4];
#pragma unroll
        for (int fr = 0; fr < 4; fr++) {
            int nn = nb + cb + (fr >> 1) * 8;
            int ii = i0 + rl + (fr & 1) * 8;
            float f0 = Sf[nn * 132 + ii];
            float f1 = Sf[(nn + 1) * 132 + ii];
            ah[fr] = pack_hi(f0, f1);
            al[fr] = pack_lo(f0, f1);
        }
        uint32_t bh[4][2], bl[4][2];
#pragma unroll
        for (int jt = 0; jt < 4; jt++) {
            int jj = 64 + j0 + jt * 8 + rl;
#pragma unroll
            for (int br = 0; br < 2; br++) {
                int nn = nb + cb + br * 8;
                float f0 = Sf[nn * 132 + jj];
                float f1 = Sf[(nn + 1) * 132 + jj];
                bh[jt][br] = pack_hi(f0, f1);
                bl[jt][br] = pack_lo(f0, f1);
            }
        }
#pragma unroll
        for (int jt = 0; jt < 4; jt++) mma16(p[jt], ah, bh[jt]);
#pragma unroll
        for (int jt = 0; jt < 4; jt++) mma16(p[jt], ah, bl[jt]);
#pragma unroll
        for (int jt = 0; jt < 4; jt++) mma16(p[jt], al, bh[jt]);
    }

#pragma unroll
    for (int jt = 0; jt < 4; jt++) {
        size_t base = (((size_t)(b * 256 + ch) * 64) + i0 + rl) * 64 + j0 + jt * 8 + cb;
        *(float2*)&g_spart[base] = make_float2(p[jt][0], p[jt][1]);
        *(float2*)&g_spart[base + 8 * 64] = make_float2(p[jt][2], p[jt][3]);
    }
}

// ---------------------------------------------------------------------------
// K3: reduce 256 Gram partials + row softmax; emit beta in fragment layout
// ---------------------------------------------------------------------------
__global__ __launch_bounds__(256) void softmax_kernel()
{
    const int m = blockIdx.x, b = blockIdx.y;
    const int tid = threadIdx.x;
    const int j = tid & 63, cp = tid >> 6;

    float s = 0.f;
    const float* base = g_spart + (((size_t)(b * 256 + cp * 64)) * 64 + m) * 64 + j;
#pragma unroll 4
    for (int cc = 0; cc < 64; cc++)
        s += base[(size_t)cc * 4096];

    __shared__ float red[4][64];
    __shared__ float r2[64];
    red[cp][j] = s;
    __syncthreads();
    float tot = red[0][j] + red[1][j] + red[2][j] + red[3][j];

    if (cp == 0) r2[j] = tot;
    __syncthreads();
    for (int o = 32; o > 0; o >>= 1) {
        if (cp == 0 && j < o) r2[j] = fmaxf(r2[j], r2[j + o]);
        __syncthreads();
    }
    float mx = r2[0];
    __syncthreads();
    float e = expf(tot - mx);
    if (cp == 0) r2[j] = e;
    __syncthreads();
    for (int o = 32; o > 0; o >>= 1) {
        if (cp == 0 && j < o) r2[j] += r2[j + o];
        __syncthreads();
    }
    if (cp == 0) {
        float val = e / r2[0];
        __half hi = __float2half(val);
        __half lo = __float2half(val - __half2float(hi));
        int t = m >> 4;
        size_t bb = (size_t)b * 8192;
        g_betaf[bb + bfrag_idx(t, 0, j >> 3, 8, m & 15, j & 7)] = hi;
        g_betaf[bb + bfrag_idx(t, 1, j >> 3, 8, m & 15, j & 7)] = lo;
    }
}

// ---------------------------------------------------------------------------
// K4: av GEMM fp16x3 (round-14 version; Os stride 66)
// ---------------------------------------------------------------------------
#define ABUF_AV 3072
#define OSST 66
#define SMEM_AV 28672

__global__ __launch_bounds__(256) void av_gemm()
{
    extern __shared__ __half smh[];
    __half* Ab0 = smh;
    __half* Ab1 = smh + ABUF_AV;
    __half* Bf  = smh + 2 * ABUF_AV;   // 8192 halfs

    const int tid = threadIdx.x;
    const int wid = tid >> 5, lane = tid & 31;
    const int wm = wid & 1, wn = wid >> 1;
    const int j0 = blockIdx.x;          // 0..255
    const int b  = blockIdx.y;
    const int n0 = j0 * 64;

    const int ar = tid >> 2;
    const int ac = (tid & 3) * 4;

    float acc[2][2][4];
#pragma unroll
    for (int i = 0; i < 2; i++)
#pragma unroll
        for (int j = 0; j < 2; j++)
#pragma unroll
            for (int q = 0; q < 4; q++) acc[i][j][q] = 0.f;

    float4 areg;
    auto ldgA = [&](int t) {
        areg = *(const float4*)(g_v + (size_t)(b * NVOX + n0 + ar) * C8 + t * 16 + ac);
    };
    auto stsA = [&](__half* Ab) {
        float vv[4] = {areg.x, areg.y, areg.z, areg.w};
        __half h[4], l[4];
#pragma unroll
        for (int q = 0; q < 4; q++) {
            h[q] = __float2half(vv[q]);
            l[q] = __float2half(vv[q] - __half2float(h[q]));
        }
        *(uint2*)&Ab[ar * 24 + ac] = *(uint2*)h;
        *(uint2*)&Ab[(64 + ar) * 24 + ac] = *(uint2*)l;
    };

    {
        const __half* src = g_betaf + (size_t)b * 8192;
#pragma unroll
        for (int i = 0; i < 4; i++) {
            int v = tid + i * 256;
            cpasync16(&Bf[v * 8], src + v * 8);
        }
        cpcommit();
    }
    ldgA(0);
    stsA(Ab0);
    cpwait0();
    __syncthreads();

#pragma unroll
    for (int t = 0; t < 4; t++) {
        __half* Ac = (t & 1) ? Ab1 : Ab0;
        __half* An = (t & 1) ? Ab0 : Ab1;
        if (t + 1 < 4) ldgA(t + 1);

        uint32_t af[2][2][4];
#pragma unroll
        for (int mi = 0; mi < 2; mi++)
#pragma unroll
            for (int hl = 0; hl < 2; hl++)
                ldmat4(af[mi][hl],
                       &Ac[(hl * 64 + wm * 32 + mi * 16 + (lane & 15)) * 24 + (lane >> 4) * 8]);
        uint32_t bh[2][2], bl[2][2];
#pragma unroll
        for (int ni = 0; ni < 2; ni++) {
            int ntile = wn * 2 + ni;
            *(uint2*)bh[ni] = *(const uint2*)&Bf[(((t * 2 + 0) * 8 + ntile) * 32 + lane) * 4];
            *(uint2*)bl[ni] = *(const uint2*)&Bf[(((t * 2 + 1) * 8 + ntile) * 32 + lane) * 4];
        }
#pragma unroll
        for (int ni = 0; ni < 2; ni++)
#pragma unroll
            for (int mi = 0; mi < 2; mi++)
                mma16(acc[mi][ni], af[mi][0], bh[ni]);
#pragma unroll
        for (int ni = 0; ni < 2; ni++)
#pragma unroll
            for (int mi = 0; mi < 2; mi++)
                mma16(acc[mi][ni], af[mi][0], bl[ni]);
#pragma unroll
        for (int ni = 0; ni < 2; ni++)
#pragma unroll
            for (int mi = 0; mi < 2; mi++)
                mma16(acc[mi][ni], af[mi][1], bh[ni]);

        if (t + 1 < 4) { stsA(An); __syncthreads(); }
    }

    __syncthreads();
    float* Os = (float*)smh;
    const int gid = lane >> 2, tg = lane & 3;
#pragma unroll
    for (int mi = 0; mi < 2; mi++) {
        int r = wm * 32 + mi * 16 + gid;
#pragma unroll
        for (int ni = 0; ni < 2; ni++) {
            int c = wn * 16 + ni * 8 + tg * 2;
            *(float2*)&Os[r * OSST + c] = make_float2(acc[mi][ni][0], acc[mi][ni][1]);
            *(float2*)&Os[(r + 8) * OSST + c] = make_float2(acc[mi][ni][2], acc[mi][ni][3]);
        }
    }
    __syncthreads();

    const int oi = tid >> 2, seg = tid & 3;
    float* dst = g_Ag + ((size_t)(b * NVOX + oi * 256 + j0)) * 64;
#pragma unroll
    for (int q = 0; q < 4; q++) {
        int d0 = seg * 16 + q * 4;
        float4 val = make_float4(Os[(d0 + 0) * OSST + oi], Os[(d0 + 1) * OSST + oi],
                                 Os[(d0 + 2) * OSST + oi], Os[(d0 + 3) * OSST + oi]);
        *(float4*)&dst[d0] = val;
    }
}

// ---------------------------------------------------------------------------
// K5: proj GEMM fp16x3 (round-14 version)
// ---------------------------------------------------------------------------
#define ABUF_P 3072
#define SMEM_PROJ ((2 * ABUF_P + 2 * 8192) * 2)  // 45056 B

__global__ __launch_bounds__(256, 2) void gemm_proj(float* __restrict__ Out)
{
    extern __shared__ __half smh[];
    __half* Ab0 = smh;
    __half* Ab1 = smh + ABUF_P;
    __half* Bb0 = smh + 2 * ABUF_P;
    __half* Bb1 = smh + 2 * ABUF_P + 8192;

    const int tid = threadIdx.x;
    const int wid = tid >> 5, lane = tid & 31;
    const int wm = wid & 1, wn = wid >> 1;
    const int nh = blockIdx.x;
    const int m0 = blockIdx.y * 64;

    const int ar = tid >> 2;
    const int ac = (tid & 3) * 4;

    float acc[2][8][4];
#pragma unroll
    for (int i = 0; i < 2; i++)
#pragma unroll
        for (int j = 0; j < 8; j++)
#pragma unroll
            for (int q = 0; q < 4; q++) acc[i][j][q] = 0.f;

    float4 areg;

    auto ldgA = [&](int t) {
        areg = *(const float4*)(g_Ag + (size_t)(m0 + ar) * C8 + t * 16 + ac);
    };
    auto stsA = [&](__half* Ab) {
        float vv[4] = {areg.x, areg.y, areg.z, areg.w};
        __half h[4], l[4];
#pragma unroll
        for (int q = 0; q < 4; q++) {
            h[q] = __float2half(vv[q]);
            l[q] = __float2half(vv[q] - __half2float(h[q]));
        }
        *(uint2*)&Ab[ar * 24 + ac] = *(uint2*)h;
        *(uint2*)&Ab[(64 + ar) * 24 + ac] = *(uint2*)l;
    };
    auto cpB = [&](int t, __half* Bb) {
#pragma unroll
        for (int hl = 0; hl < 2; hl++) {
            const __half* src = g_W2f + ((size_t)(t * 2 + hl) * 64 + nh * 32) * 128;
#pragma unroll
            for (int i = 0; i < 2; i++) {
                int v = tid + i * 256;
                cpasync16(&Bb[hl * 4096 + v * 8], src + v * 8);
            }
        }
        cpcommit();
    };
    auto compute = [&](const __half* Ab, const __half* Bb) {
        uint32_t af[2][2][4];
#pragma unroll
        for (int mi = 0; mi < 2; mi++)
#pragma unroll
            for (int hl = 0; hl < 2; hl++)
                ldmat4(af[mi][hl],
                       &Ab[(hl * 64 + wm * 32 + mi * 16 + (lane & 15)) * 24 + (lane >> 4) * 8]);
        uint32_t bh[8][2], bl[8][2];
#pragma unroll
        for (int ni = 0; ni < 8; ni++) {
            int ntl = wn * 8 + ni;
            *(uint2*)bh[ni] = *(const uint2*)&Bb[(ntl * 32 + lane) * 4];
            *(uint2*)bl[ni] = *(const uint2*)&Bb[4096 + (ntl * 32 + lane) * 4];
        }
#pragma unroll
        for (int ni = 0; ni < 8; ni++)
#pragma unroll
            for (int mi = 0; mi < 2; mi++)
                mma16(acc[mi][ni], af[mi][0], bh[ni]);
#pragma unroll
        for (int ni = 0; ni < 8; ni++)
#pragma unroll
            for (int mi = 0; mi < 2; mi++)
                mma16(acc[mi][ni], af[mi][0], bl[ni]);
#pragma unroll
        for (int ni = 0; ni < 8; ni++)
#pragma unroll
            for (int mi = 0; mi < 2; mi++)
                mma16(acc[mi][ni], af[mi][1], bh[ni]);
    };

    ldgA(0);
    cpB(0, Bb0);
    stsA(Ab0);

    for (int t = 0; t < 4; t++) {
        __half* Ac = (t & 1) ? Ab1 : Ab0;
        __half* Bc = (t & 1) ? Bb1 : Bb0;
        __half* An = (t & 1) ? Ab0 : Ab1;
        __half* Bn = (t & 1) ? Bb0 : Bb1;
        if (t + 1 < 4) ldgA(t + 1);
        cpwait0();
        __syncthreads();
        if (t + 1 < 4) cpB(t + 1, Bn);
        compute(Ac, Bc);
        if (t + 1 < 4) stsA(An);
    }

    const int gid = lane >> 2, tg = lane & 3;
#pragma unroll
    for (int mi = 0; mi < 2; mi++) {
        int r0 = m0 + wm * 32 + mi * 16 + gid;
#pragma unroll
        for (int ni = 0; ni < 8; ni++) {
            int col = nh * 256 + wn * 64 + ni * 8 + tg * 2;
            float b0 = g_b2[col], b1 = g_b2[col + 1];
            float2 v0 = make_float2(acc[mi][ni][0] + b0, acc[mi][ni][1] + b1);
            float2 v1 = make_float2(acc[mi][ni][2] + b0, acc[mi][ni][3] + b1);
            *(float2*)&Out[(size_t)r0 * CC + col] = v0;
            *(float2*)&Out[(size_t)(r0 + 8) * CC + col] = v1;
        }
    }
}

// ---------------------------------------------------------------------------
extern "C" void kernel_launch(void* const* d_in, const int* in_sizes, int n_in,
                              void* d_out, int out_size)
{
    const float* x   = (const float*)d_in[0];
    const float* g1  = (const float*)d_in[1];
    const float* be1 = (const float*)d_in[2];
    const float* m1  = (const float*)d_in[3];
    const float* v1  = (const float*)d_in[4];
    const float* wq  = (const float*)d_in[5];
    const float* bq  = (const float*)d_in[6];
    const float* wk  = (const float*)d_in[7];
    const float* bk  = (const float*)d_in[8];
    const float* wv  = (const float*)d_in[9];
    const float* bv  = (const float*)d_in[10];
    const float* wp  = (const float*)d_in[11];
    const float* bp  = (const float*)d_in[12];
    const float* g2  = (const float*)d_in[13];
    const float* be2 = (const float*)d_in[14];
    const float* m2  = (const float*)d_in[15];
    const float* v2  = (const float*)d_in[16];
    float* out = (float*)d_out;

    cudaFuncSetAttribute(gemm_qkv,  cudaFuncAttributeMaxDynamicSharedMemorySize, SMEM_QKV);
    cudaFuncSetAttribute(gemm_proj, cudaFuncAttributeMaxDynamicSharedMemorySize, SMEM_PROJ);

    prep_kernel<<<200, 256>>>(g1, be1, m1, v1, wq, bq, wk, bk, wv, bv,
                              wp, bp, g2, be2, m2, v2);

    // QKV GEMM + fused per-CTA Gram partials (3-stage B ring)
    gemm_qkv<<<(BB * NVOX) / 64, 256, SMEM_QKV>>>(x);

    // reduce partials + softmax -> beta fragments
    softmax_kernel<<<dim3(64, BB), 256>>>();

    // A = v @ beta via tensor cores (pre-permuted store)
    av_gemm<<<dim3(NVOX / 64, BB), 256, SMEM_AV>>>();

    // proj GEMM
    gemm_proj<<<dim3(2, (BB * NVOX) / 64), 256, SMEM_PROJ>>>(out);
}